// round 15
// baseline (speedup 1.0000x reference)
#include <cuda_runtime.h>
#include <cuda_bf16.h>
#include <mma.h>
#include <cstdint>

using namespace nvcuda;

// ---------------------------------------------------------------------------
// CorrelationHead: corr(patch1,patch2) -> FC1(relu) -> FC2(relu) -> FC3
// Sparse fact: only 625 of 12544 correlation features are nonzero.
// FC1/FC2: WMMA bf16 (HMMA path; tcgen05 unavailable under compute_103 PTX),
// split-3 precision (A'=[hi|lo|hi], B'=[hi|hi|lo], fp32 accumulate).
// R14 verified correctness (rel_err 9.7e-6) but was latency-bound
// (issue=12%, 4 warps/CTA, 1.73-wave tail). This round: 128x64 CTA tile,
// 8 warps, single-wave grid (128 CTAs), same fragment semantics.
// ---------------------------------------------------------------------------

#define B_ROIS 1024
#define K1     640            // padded sparse K (625 -> 640)
#define REP    1024
#define K1P    (3 * K1)       // 1920
#define K2P    (3 * REP)      // 3072

__device__ const int d_AI [25] = {6, 4,5,6, 2,3,4,5,6, 0,1,2,3,4,5,6, 0,1,2,3,4, 0,1,2, 0};
__device__ const int d_AI2[25] = {0, 0,1,2, 0,1,2,3,4, 0,1,2,3,4,5,6, 2,3,4,5,6, 4,5,6, 6};

// Scratch (device globals; no runtime allocation allowed).
__device__ __nv_bfloat16 g_W1b [REP * K1P];     // B-side FC1  [n][k'] hi|hi|lo
__device__ __nv_bfloat16 g_W2b [REP * K2P];     // B-side FC2  [n][k'] hi|hi|lo
__device__ __nv_bfloat16 g_corrb[B_ROIS * K1P]; // A-side FC1  [m][k'] hi|lo|hi
__device__ __nv_bfloat16 g_Y1b [B_ROIS * K2P];  // A-side FC2  [m][k'] hi|lo|hi
__device__ float         g_Y2  [B_ROIS * REP];

// ======================= W1 gather + split (B-side: hi|hi|lo) ===============
__global__ void gather_w1_b(const float* __restrict__ W1, __nv_bfloat16* __restrict__ W1b)
{
    int idx = blockIdx.x * 256 + threadIdx.x;
    if (idx >= REP * K1) return;
    int n = idx / K1;
    int k = idx - n * K1;
    float v = 0.f;
    if (k < 625) {
        int a  = k / 25;
        int bc = k - a * 25;
        int i  = d_AI[a],  i2 = d_AI2[a];
        int j  = d_AI[bc], j2 = d_AI2[bc];
        int ph = 7 + ((i2 - i) >> 1);
        int pw = 7 + ((j2 - j) >> 1);
        int f  = (ph * 16 + pw) * 49 + i * 7 + j;
        v = W1[n * 12544 + f];
    }
    __nv_bfloat16 hi = __float2bfloat16(v);
    __nv_bfloat16 lo = __float2bfloat16(v - __bfloat162float(hi));
    size_t rb = (size_t)n * K1P;
    W1b[rb + k]          = hi;
    W1b[rb + K1 + k]     = hi;
    W1b[rb + 2 * K1 + k] = lo;
}

// ======================= W2 split (B-side: hi|hi|lo) ========================
__global__ void cvt_w2_b(const float* __restrict__ W2, __nv_bfloat16* __restrict__ W2b)
{
    int idx = blockIdx.x * 256 + threadIdx.x;
    if (idx >= REP * REP) return;
    int n = idx >> 10;
    int k = idx & 1023;
    float v = W2[idx];
    __nv_bfloat16 hi = __float2bfloat16(v);
    __nv_bfloat16 lo = __float2bfloat16(v - __bfloat162float(hi));
    size_t rb = (size_t)n * K2P;
    W2b[rb + k]           = hi;
    W2b[rb + REP + k]     = hi;
    W2b[rb + 2 * REP + k] = lo;
}

// ======================= correlation -> split bf16 (A-side: hi|lo|hi) =======
#define CORR_SMEM (2 * 12544 * 4)

__global__ void __launch_bounds__(256) corr_kernel(const float* __restrict__ p1,
                                                   const float* __restrict__ p2,
                                                   __nv_bfloat16* __restrict__ corrb)
{
    extern __shared__ float sm[];
    float* s1 = sm;
    float* s2 = sm + 12544;

    int b   = blockIdx.x;
    int tid = threadIdx.x;
    const float4* g1 = (const float4*)(p1 + b * 12544);
    const float4* g2 = (const float4*)(p2 + b * 12544);
    for (int i = tid; i < 3136; i += 256) {
        ((float4*)s1)[i] = g1[i];
        ((float4*)s2)[i] = g2[i];
    }
    __syncthreads();

    int warp = tid >> 5, lane = tid & 31;
    float acc[25];
    if (lane < 25) {
        constexpr int AI [25] = {6, 4,5,6, 2,3,4,5,6, 0,1,2,3,4,5,6, 0,1,2,3,4, 0,1,2, 0};
        constexpr int AI2[25] = {0, 0,1,2, 0,1,2,3,4, 0,1,2,3,4,5,6, 2,3,4,5,6, 4,5,6, 6};
        int j  = d_AI[lane];
        int j2 = d_AI2[lane];
#pragma unroll
        for (int a = 0; a < 25; ++a) acc[a] = 0.f;
        const float* s1w = s1 + warp * 32 * 49 + j;
        const float* s2w = s2 + warp * 32 * 49 + j2;
#pragma unroll 4
        for (int cc = 0; cc < 32; ++cc) {
            float v1[7], v2[7];
#pragma unroll
            for (int i = 0; i < 7; ++i) {
                v1[i] = s1w[cc * 49 + i * 7];
                v2[i] = s2w[cc * 49 + i * 7];
            }
#pragma unroll
            for (int a = 0; a < 25; ++a)
                acc[a] = fmaf(v1[AI[a]], v2[AI2[a]], acc[a]);
        }
    }
    __syncthreads();

    float* red = sm;   // [25][256]
    if (lane < 25) {
#pragma unroll
        for (int a = 0; a < 25; ++a)
            red[a * 256 + warp * 32 + lane] = acc[a];
    }
    __syncthreads();

    size_t rb = (size_t)b * K1P;
    for (int k = tid; k < 625; k += 256) {
        int a  = k / 25;
        int bc = k - a * 25;
        float s = 0.f;
#pragma unroll
        for (int w = 0; w < 8; ++w) s += red[a * 256 + w * 32 + bc];
        __nv_bfloat16 hi = __float2bfloat16(s);
        __nv_bfloat16 lo = __float2bfloat16(s - __bfloat162float(hi));
        corrb[rb + k]          = hi;   // A-side: hi | lo | hi
        corrb[rb + K1 + k]     = lo;
        corrb[rb + 2 * K1 + k] = hi;
    }
    if (tid < 15) {
        int k = 625 + tid;
        __nv_bfloat16 z = __float2bfloat16(0.f);
        corrb[rb + k] = z; corrb[rb + K1 + k] = z; corrb[rb + 2 * K1 + k] = z;
    }
}

// ======================= WMMA bf16 GEMM (HMMA path, v2) =====================
// C[m][n] = relu( sum_k A[m][k]*Bt[n][k] + bias[n] )
// A: [M][Kp] bf16 row-major, Bt: [N][Kp] bf16 row-major.
// 128x64 CTA tile, 256 threads = 8 warps (4 in M x 2 in N), warp tile 32x32
// (2x2 frags of 16x16x16). K-step 32, double-buffered smem + reg prefetch.
// Grid (Nt/64, M/128) = (16, 8) = 128 CTAs -> single wave on 148 SMs.
// EPI 0: fp32 out [m][Nt] (+relu).  EPI 1: split-3 bf16 A-side [m][3*Nt].
template <int EPI>
__global__ void __launch_bounds__(256) gemm_wmma(const __nv_bfloat16* __restrict__ A,
                                                 const __nv_bfloat16* __restrict__ Bt,
                                                 const float* __restrict__ bias,
                                                 void* __restrict__ outp,
                                                 int Nt, int Kp)
{
    __shared__ __nv_bfloat16 As[2][128][40];  // [buf][row m][k] (+8 pad)
    __shared__ __nv_bfloat16 Bs[2][64][40];   // [buf][row n][k] (+8 pad)
    __shared__ float stage[8][16][16];        // per-warp epilogue patch

    int tid  = threadIdx.x;
    int wid  = tid >> 5;
    int lane = tid & 31;
    int wm = wid & 3;          // 4 warps in M (32 rows each)
    int wn = wid >> 2;         // 2 warps in N (32 cols each)

    const int m0 = blockIdx.y * 128;
    const int n0 = blockIdx.x * 64;

    const __nv_bfloat16* Ag = A  + (size_t)m0 * Kp;
    const __nv_bfloat16* Bg = Bt + (size_t)n0 * Kp;

    // Tile-load maps (rows of 32 k bf16 = 64B = 8 uint4 per... 32 bf16 = 64B
    // = 4 uint4 per row).  A: 128 rows x 4 = 512 uint4, 2/thread.
    //                      B:  64 rows x 4 = 256 uint4, 1/thread.
    // A idx u in {tid, tid+256}: row = u>>2, col = (u&3)*8.
    // B idx tid: row = tid>>2, col = (tid&3)*8.
    int ar0 = tid >> 2,          ac0 = (tid & 3) * 8;
    int ar1 = (tid + 256) >> 2,  ac1 = ac0;           // (u&3) identical
    int br  = tid >> 2,          bc  = (tid & 3) * 8; // only tid<256 used (all)

    wmma::fragment<wmma::accumulator, 16, 16, 16, float> acc[2][2];
#pragma unroll
    for (int i = 0; i < 2; ++i)
#pragma unroll
        for (int j = 0; j < 2; ++j) wmma::fill_fragment(acc[i][j], 0.0f);

    // Prologue: k-tile 0 into buffer 0.
    *(uint4*)&As[0][ar0][ac0] = *(const uint4*)&Ag[(size_t)ar0 * Kp + ac0];
    *(uint4*)&As[0][ar1][ac1] = *(const uint4*)&Ag[(size_t)ar1 * Kp + ac1];
    *(uint4*)&Bs[0][br ][bc ] = *(const uint4*)&Bg[(size_t)br  * Kp + bc ];
    __syncthreads();

    int buf = 0;
    for (int kt = 0; kt < Kp; kt += 32) {
        // Prefetch next k-tile into registers.
        uint4 pa0, pa1, pb0;
        bool has_next = (kt + 32) < Kp;
        if (has_next) {
            const __nv_bfloat16* An = Ag + kt + 32;
            const __nv_bfloat16* Bn = Bg + kt + 32;
            pa0 = *(const uint4*)&An[(size_t)ar0 * Kp + ac0];
            pa1 = *(const uint4*)&An[(size_t)ar1 * Kp + ac1];
            pb0 = *(const uint4*)&Bn[(size_t)br  * Kp + bc ];
        }

        // Compute on current buffer: two k16 sub-steps.
#pragma unroll
        for (int kk = 0; kk < 32; kk += 16) {
            wmma::fragment<wmma::matrix_a, 16, 16, 16, __nv_bfloat16, wmma::row_major> af[2];
            wmma::fragment<wmma::matrix_b, 16, 16, 16, __nv_bfloat16, wmma::col_major> bf[2];
#pragma unroll
            for (int i = 0; i < 2; ++i)
                wmma::load_matrix_sync(af[i], &As[buf][wm * 32 + i * 16][kk], 40);
#pragma unroll
            for (int j = 0; j < 2; ++j)
                wmma::load_matrix_sync(bf[j], &Bs[buf][wn * 32 + j * 16][kk], 40);
#pragma unroll
            for (int i = 0; i < 2; ++i)
#pragma unroll
                for (int j = 0; j < 2; ++j)
                    wmma::mma_sync(acc[i][j], af[i], bf[j], acc[i][j]);
        }

        if (has_next) {
            int nb = buf ^ 1;
            *(uint4*)&As[nb][ar0][ac0] = pa0;
            *(uint4*)&As[nb][ar1][ac1] = pa1;
            *(uint4*)&Bs[nb][br ][bc ] = pb0;
            __syncthreads();
            buf = nb;
        }
    }

    // Epilogue: each warp stages its 16x16 fragments, applies bias+relu, emits.
#pragma unroll
    for (int i = 0; i < 2; ++i) {
#pragma unroll
        for (int j = 0; j < 2; ++j) {
            wmma::store_matrix_sync(&stage[wid][0][0], acc[i][j], 16, wmma::mem_row_major);
            __syncwarp();
#pragma unroll
            for (int e = 0; e < 8; ++e) {
                int idx = lane * 8 + e;          // 0..255
                int rr = idx >> 4, cc = idx & 15;
                int m = m0 + wm * 32 + i * 16 + rr;
                int n = n0 + wn * 32 + j * 16 + cc;
                float v = stage[wid][rr][cc] + bias[n];
                v = fmaxf(v, 0.f);
                if (EPI == 0) {
                    ((float*)outp)[(size_t)m * Nt + n] = v;
                } else {
                    __nv_bfloat16 hi = __float2bfloat16(v);
                    __nv_bfloat16 lo = __float2bfloat16(v - __bfloat162float(hi));
                    __nv_bfloat16* O = (__nv_bfloat16*)outp;
                    size_t rb = (size_t)m * 3 * Nt;
                    O[rb + n]          = hi;     // A-side: hi | lo | hi
                    O[rb + Nt + n]     = lo;
                    O[rb + 2 * Nt + n] = hi;
                }
            }
            __syncwarp();
        }
    }
}

// ======================= FC3 ================================================
__global__ void __launch_bounds__(128) fc3_kernel(const float* __restrict__ Y,
                                                  const float* __restrict__ W3,
                                                  const float* __restrict__ b3,
                                                  float* __restrict__ out)
{
    int b = blockIdx.x;
    int warp = threadIdx.x >> 5, lane = threadIdx.x & 31;
    const float* y = Y  + (size_t)b * REP;
    const float* w = W3 + (size_t)warp * REP;
    float s = 0.f;
#pragma unroll 8
    for (int k = lane; k < REP; k += 32) s = fmaf(y[k], w[k], s);
#pragma unroll
    for (int off = 16; off > 0; off >>= 1)
        s += __shfl_down_sync(0xffffffff, s, off);
    if (lane == 0) out[b * 4 + warp] = s + b3[warp];
}

// ---------------------------------------------------------------------------
extern "C" void kernel_launch(void* const* d_in, const int* in_sizes, int n_in,
                              void* d_out, int out_size)
{
    const float* patch1 = (const float*)d_in[0];
    const float* patch2 = (const float*)d_in[1];
    const float* W1     = (const float*)d_in[2];
    const float* b1     = (const float*)d_in[3];
    const float* W2     = (const float*)d_in[4];
    const float* b2     = (const float*)d_in[5];
    const float* W3     = (const float*)d_in[6];
    const float* b3     = (const float*)d_in[7];
    float* out = (float*)d_out;

    __nv_bfloat16 *pW1b, *pW2b, *pCorrb, *pY1b;
    float *pY2;
    cudaGetSymbolAddress((void**)&pW1b, g_W1b);
    cudaGetSymbolAddress((void**)&pW2b, g_W2b);
    cudaGetSymbolAddress((void**)&pCorrb, g_corrb);
    cudaGetSymbolAddress((void**)&pY1b, g_Y1b);
    cudaGetSymbolAddress((void**)&pY2, g_Y2);

    cudaFuncSetAttribute(corr_kernel,
                         cudaFuncAttributeMaxDynamicSharedMemorySize, CORR_SMEM);

    gather_w1_b<<<(REP * K1 + 255) / 256, 256>>>(W1, pW1b);
    cvt_w2_b<<<(REP * REP + 255) / 256, 256>>>(W2, pW2b);
    corr_kernel<<<B_ROIS, 256, CORR_SMEM>>>(patch1, patch2, pCorrb);
    gemm_wmma<1><<<dim3(16, 8), 256>>>(pCorrb, pW1b, b1, pY1b, REP, K1P);
    gemm_wmma<0><<<dim3(16, 8), 256>>>(pY1b,  pW2b, b2, pY2,  REP, K2P);
    fc3_kernel<<<B_ROIS, 128>>>(pY2, W3, b3, out);
}

// round 16
// speedup vs baseline: 1.0687x; 1.0687x over previous
#include <cuda_runtime.h>
#include <cuda_bf16.h>
#include <mma.h>
#include <cstdint>

using namespace nvcuda;

// ---------------------------------------------------------------------------
// CorrelationHead: corr(patch1,patch2) -> FC1(relu) -> FC2(relu) -> FC3
// Sparse fact: only 625 of 12544 correlation features are nonzero.
// FC1/FC2: WMMA bf16 (HMMA path; tcgen05 unavailable under compute_103 PTX),
// split-3 precision (A'=[hi|lo|hi], B'=[hi|hi|lo], fp32 accumulate).
// R14/R15 showed issue stuck at 12% independent of warp count ->
// accumulator-ILP starvation (4 chains). This round: warp tile 32x64
// (8 acc chains), CTA 64x128, 4 warps, grid 128 = single wave.
// ---------------------------------------------------------------------------

#define B_ROIS 1024
#define K1     640            // padded sparse K (625 -> 640)
#define REP    1024
#define K1P    (3 * K1)       // 1920
#define K2P    (3 * REP)      // 3072

__device__ const int d_AI [25] = {6, 4,5,6, 2,3,4,5,6, 0,1,2,3,4,5,6, 0,1,2,3,4, 0,1,2, 0};
__device__ const int d_AI2[25] = {0, 0,1,2, 0,1,2,3,4, 0,1,2,3,4,5,6, 2,3,4,5,6, 4,5,6, 6};

// Scratch (device globals; no runtime allocation allowed).
__device__ __nv_bfloat16 g_W1b [REP * K1P];     // B-side FC1  [n][k'] hi|hi|lo
__device__ __nv_bfloat16 g_W2b [REP * K2P];     // B-side FC2  [n][k'] hi|hi|lo
__device__ __nv_bfloat16 g_corrb[B_ROIS * K1P]; // A-side FC1  [m][k'] hi|lo|hi
__device__ __nv_bfloat16 g_Y1b [B_ROIS * K2P];  // A-side FC2  [m][k'] hi|lo|hi
__device__ float         g_Y2  [B_ROIS * REP];

// ======================= W1 gather + split (B-side: hi|hi|lo) ===============
__global__ void gather_w1_b(const float* __restrict__ W1, __nv_bfloat16* __restrict__ W1b)
{
    int idx = blockIdx.x * 256 + threadIdx.x;
    if (idx >= REP * K1) return;
    int n = idx / K1;
    int k = idx - n * K1;
    float v = 0.f;
    if (k < 625) {
        int a  = k / 25;
        int bc = k - a * 25;
        int i  = d_AI[a],  i2 = d_AI2[a];
        int j  = d_AI[bc], j2 = d_AI2[bc];
        int ph = 7 + ((i2 - i) >> 1);
        int pw = 7 + ((j2 - j) >> 1);
        int f  = (ph * 16 + pw) * 49 + i * 7 + j;
        v = W1[n * 12544 + f];
    }
    __nv_bfloat16 hi = __float2bfloat16(v);
    __nv_bfloat16 lo = __float2bfloat16(v - __bfloat162float(hi));
    size_t rb = (size_t)n * K1P;
    W1b[rb + k]          = hi;
    W1b[rb + K1 + k]     = hi;
    W1b[rb + 2 * K1 + k] = lo;
}

// ======================= W2 split (B-side: hi|hi|lo) ========================
__global__ void cvt_w2_b(const float* __restrict__ W2, __nv_bfloat16* __restrict__ W2b)
{
    int idx = blockIdx.x * 256 + threadIdx.x;
    if (idx >= REP * REP) return;
    int n = idx >> 10;
    int k = idx & 1023;
    float v = W2[idx];
    __nv_bfloat16 hi = __float2bfloat16(v);
    __nv_bfloat16 lo = __float2bfloat16(v - __bfloat162float(hi));
    size_t rb = (size_t)n * K2P;
    W2b[rb + k]           = hi;
    W2b[rb + REP + k]     = hi;
    W2b[rb + 2 * REP + k] = lo;
}

// ======================= correlation -> split bf16 (A-side: hi|lo|hi) =======
#define CORR_SMEM (2 * 12544 * 4)

__global__ void __launch_bounds__(256) corr_kernel(const float* __restrict__ p1,
                                                   const float* __restrict__ p2,
                                                   __nv_bfloat16* __restrict__ corrb)
{
    extern __shared__ float sm[];
    float* s1 = sm;
    float* s2 = sm + 12544;

    int b   = blockIdx.x;
    int tid = threadIdx.x;
    const float4* g1 = (const float4*)(p1 + b * 12544);
    const float4* g2 = (const float4*)(p2 + b * 12544);
    for (int i = tid; i < 3136; i += 256) {
        ((float4*)s1)[i] = g1[i];
        ((float4*)s2)[i] = g2[i];
    }
    __syncthreads();

    int warp = tid >> 5, lane = tid & 31;
    float acc[25];
    if (lane < 25) {
        constexpr int AI [25] = {6, 4,5,6, 2,3,4,5,6, 0,1,2,3,4,5,6, 0,1,2,3,4, 0,1,2, 0};
        constexpr int AI2[25] = {0, 0,1,2, 0,1,2,3,4, 0,1,2,3,4,5,6, 2,3,4,5,6, 4,5,6, 6};
        int j  = d_AI[lane];
        int j2 = d_AI2[lane];
#pragma unroll
        for (int a = 0; a < 25; ++a) acc[a] = 0.f;
        const float* s1w = s1 + warp * 32 * 49 + j;
        const float* s2w = s2 + warp * 32 * 49 + j2;
#pragma unroll 4
        for (int cc = 0; cc < 32; ++cc) {
            float v1[7], v2[7];
#pragma unroll
            for (int i = 0; i < 7; ++i) {
                v1[i] = s1w[cc * 49 + i * 7];
                v2[i] = s2w[cc * 49 + i * 7];
            }
#pragma unroll
            for (int a = 0; a < 25; ++a)
                acc[a] = fmaf(v1[AI[a]], v2[AI2[a]], acc[a]);
        }
    }
    __syncthreads();

    float* red = sm;   // [25][256]
    if (lane < 25) {
#pragma unroll
        for (int a = 0; a < 25; ++a)
            red[a * 256 + warp * 32 + lane] = acc[a];
    }
    __syncthreads();

    size_t rb = (size_t)b * K1P;
    for (int k = tid; k < 625; k += 256) {
        int a  = k / 25;
        int bc = k - a * 25;
        float s = 0.f;
#pragma unroll
        for (int w = 0; w < 8; ++w) s += red[a * 256 + w * 32 + bc];
        __nv_bfloat16 hi = __float2bfloat16(s);
        __nv_bfloat16 lo = __float2bfloat16(s - __bfloat162float(hi));
        corrb[rb + k]          = hi;   // A-side: hi | lo | hi
        corrb[rb + K1 + k]     = lo;
        corrb[rb + 2 * K1 + k] = hi;
    }
    if (tid < 15) {
        int k = 625 + tid;
        __nv_bfloat16 z = __float2bfloat16(0.f);
        corrb[rb + k] = z; corrb[rb + K1 + k] = z; corrb[rb + 2 * K1 + k] = z;
    }
}

// ======================= WMMA bf16 GEMM (HMMA path, v3) =====================
// C[m][n] = relu( sum_k A[m][k]*Bt[n][k] + bias[n] )
// A: [M][Kp] bf16 row-major, Bt: [N][Kp] bf16 row-major.
// CTA tile 64(M) x 128(N), 128 threads = 4 warps (2M x 2N), warp tile 32x64
// = 2x4 fragments -> 8 independent accumulator chains per warp.
// K-step 32, double-buffered smem + register prefetch.
// Grid (Nt/128, M/64) = (8, 16) = 128 CTAs -> single wave.
// EPI 0: fp32 out [m][Nt] (+relu).  EPI 1: split-3 bf16 A-side [m][3*Nt].
template <int EPI>
__global__ void __launch_bounds__(128) gemm_wmma(const __nv_bfloat16* __restrict__ A,
                                                 const __nv_bfloat16* __restrict__ Bt,
                                                 const float* __restrict__ bias,
                                                 void* __restrict__ outp,
                                                 int Nt, int Kp)
{
    __shared__ __nv_bfloat16 As[2][64][40];   // [buf][row m][k] (+8 pad)
    __shared__ __nv_bfloat16 Bs[2][128][40];  // [buf][row n][k] (+8 pad)
    __shared__ float stage[4][16][16];        // per-warp epilogue patch

    int tid  = threadIdx.x;
    int wid  = tid >> 5;
    int lane = tid & 31;
    int wm = wid & 1;          // 2 warps in M (32 rows each)
    int wn = wid >> 1;         // 2 warps in N (64 cols each)

    const int m0 = blockIdx.y * 64;
    const int n0 = blockIdx.x * 128;

    const __nv_bfloat16* Ag = A  + (size_t)m0 * Kp;
    const __nv_bfloat16* Bg = Bt + (size_t)n0 * Kp;

    // Load maps: rows are 32 bf16 = 64 B = 4 uint4.
    // A: 64 rows x 4 = 256 uint4, 2/thread (u = tid, tid+128).
    // B: 128 rows x 4 = 512 uint4, 4/thread (u = tid + p*128, p=0..3).
    int ar0 = tid >> 2,          ac = (tid & 3) * 8;
    int ar1 = (tid + 128) >> 2;                    // (u&3) same as tid

    wmma::fragment<wmma::accumulator, 16, 16, 16, float> acc[2][4];
#pragma unroll
    for (int i = 0; i < 2; ++i)
#pragma unroll
        for (int j = 0; j < 4; ++j) wmma::fill_fragment(acc[i][j], 0.0f);

    // Prologue: k-tile 0 into buffer 0.
    *(uint4*)&As[0][ar0][ac] = *(const uint4*)&Ag[(size_t)ar0 * Kp + ac];
    *(uint4*)&As[0][ar1][ac] = *(const uint4*)&Ag[(size_t)ar1 * Kp + ac];
#pragma unroll
    for (int p = 0; p < 4; ++p) {
        int u = tid + p * 128;
        int br = u >> 2, bc = (u & 3) * 8;
        *(uint4*)&Bs[0][br][bc] = *(const uint4*)&Bg[(size_t)br * Kp + bc];
    }
    __syncthreads();

    int buf = 0;
    for (int kt = 0; kt < Kp; kt += 32) {
        // Prefetch next k-tile into registers.
        uint4 pa0, pa1, pb[4];
        bool has_next = (kt + 32) < Kp;
        if (has_next) {
            const __nv_bfloat16* An = Ag + kt + 32;
            const __nv_bfloat16* Bn = Bg + kt + 32;
            pa0 = *(const uint4*)&An[(size_t)ar0 * Kp + ac];
            pa1 = *(const uint4*)&An[(size_t)ar1 * Kp + ac];
#pragma unroll
            for (int p = 0; p < 4; ++p) {
                int u = tid + p * 128;
                int br = u >> 2, bc = (u & 3) * 8;
                pb[p] = *(const uint4*)&Bn[(size_t)br * Kp + bc];
            }
        }

        // Compute on current buffer: two k16 sub-steps, 8 acc chains.
#pragma unroll
        for (int kk = 0; kk < 32; kk += 16) {
            wmma::fragment<wmma::matrix_a, 16, 16, 16, __nv_bfloat16, wmma::row_major> af[2];
            wmma::fragment<wmma::matrix_b, 16, 16, 16, __nv_bfloat16, wmma::col_major> bf[4];
#pragma unroll
            for (int i = 0; i < 2; ++i)
                wmma::load_matrix_sync(af[i], &As[buf][wm * 32 + i * 16][kk], 40);
#pragma unroll
            for (int j = 0; j < 4; ++j)
                wmma::load_matrix_sync(bf[j], &Bs[buf][wn * 64 + j * 16][kk], 40);
#pragma unroll
            for (int i = 0; i < 2; ++i)
#pragma unroll
                for (int j = 0; j < 4; ++j)
                    wmma::mma_sync(acc[i][j], af[i], bf[j], acc[i][j]);
        }

        if (has_next) {
            int nb = buf ^ 1;
            *(uint4*)&As[nb][ar0][ac] = pa0;
            *(uint4*)&As[nb][ar1][ac] = pa1;
#pragma unroll
            for (int p = 0; p < 4; ++p) {
                int u = tid + p * 128;
                int br = u >> 2, bc = (u & 3) * 8;
                *(uint4*)&Bs[nb][br][bc] = pb[p];
            }
            __syncthreads();
            buf = nb;
        }
    }

    // Epilogue: each warp stages its 16x16 fragments, applies bias+relu, emits.
#pragma unroll
    for (int i = 0; i < 2; ++i) {
#pragma unroll
        for (int j = 0; j < 4; ++j) {
            wmma::store_matrix_sync(&stage[wid][0][0], acc[i][j], 16, wmma::mem_row_major);
            __syncwarp();
#pragma unroll
            for (int e = 0; e < 8; ++e) {
                int idx = lane * 8 + e;          // 0..255
                int rr = idx >> 4, cc = idx & 15;
                int m = m0 + wm * 32 + i * 16 + rr;
                int n = n0 + wn * 64 + j * 16 + cc;
                float v = stage[wid][rr][cc] + bias[n];
                v = fmaxf(v, 0.f);
                if (EPI == 0) {
                    ((float*)outp)[(size_t)m * Nt + n] = v;
                } else {
                    __nv_bfloat16 hi = __float2bfloat16(v);
                    __nv_bfloat16 lo = __float2bfloat16(v - __bfloat162float(hi));
                    __nv_bfloat16* O = (__nv_bfloat16*)outp;
                    size_t rb = (size_t)m * 3 * Nt;
                    O[rb + n]          = hi;     // A-side: hi | lo | hi
                    O[rb + Nt + n]     = lo;
                    O[rb + 2 * Nt + n] = hi;
                }
            }
            __syncwarp();
        }
    }
}

// ======================= FC3 ================================================
__global__ void __launch_bounds__(128) fc3_kernel(const float* __restrict__ Y,
                                                  const float* __restrict__ W3,
                                                  const float* __restrict__ b3,
                                                  float* __restrict__ out)
{
    int b = blockIdx.x;
    int warp = threadIdx.x >> 5, lane = threadIdx.x & 31;
    const float* y = Y  + (size_t)b * REP;
    const float* w = W3 + (size_t)warp * REP;
    float s = 0.f;
#pragma unroll 8
    for (int k = lane; k < REP; k += 32) s = fmaf(y[k], w[k], s);
#pragma unroll
    for (int off = 16; off > 0; off >>= 1)
        s += __shfl_down_sync(0xffffffff, s, off);
    if (lane == 0) out[b * 4 + warp] = s + b3[warp];
}

// ---------------------------------------------------------------------------
extern "C" void kernel_launch(void* const* d_in, const int* in_sizes, int n_in,
                              void* d_out, int out_size)
{
    const float* patch1 = (const float*)d_in[0];
    const float* patch2 = (const float*)d_in[1];
    const float* W1     = (const float*)d_in[2];
    const float* b1     = (const float*)d_in[3];
    const float* W2     = (const float*)d_in[4];
    const float* b2     = (const float*)d_in[5];
    const float* W3     = (const float*)d_in[6];
    const float* b3     = (const float*)d_in[7];
    float* out = (float*)d_out;

    __nv_bfloat16 *pW1b, *pW2b, *pCorrb, *pY1b;
    float *pY2;
    cudaGetSymbolAddress((void**)&pW1b, g_W1b);
    cudaGetSymbolAddress((void**)&pW2b, g_W2b);
    cudaGetSymbolAddress((void**)&pCorrb, g_corrb);
    cudaGetSymbolAddress((void**)&pY1b, g_Y1b);
    cudaGetSymbolAddress((void**)&pY2, g_Y2);

    cudaFuncSetAttribute(corr_kernel,
                         cudaFuncAttributeMaxDynamicSharedMemorySize, CORR_SMEM);

    gather_w1_b<<<(REP * K1 + 255) / 256, 256>>>(W1, pW1b);
    cvt_w2_b<<<(REP * REP + 255) / 256, 256>>>(W2, pW2b);
    corr_kernel<<<B_ROIS, 256, CORR_SMEM>>>(patch1, patch2, pCorrb);
    gemm_wmma<1><<<dim3(8, 16), 128>>>(pCorrb, pW1b, b1, pY1b, REP, K1P);
    gemm_wmma<0><<<dim3(8, 16), 128>>>(pY1b,  pW2b, b2, pY2,  REP, K2P);
    fc3_kernel<<<B_ROIS, 128>>>(pY2, W3, b3, out);
}